// round 2
// baseline (speedup 1.0000x reference)
#include <cuda_runtime.h>
#include <math.h>

#define TT 8192
#define NBLK 16   // blocks per direction in the LSTM kernel

// ---------------- scratch (static device globals; no allocation) ----------
__device__ float    g_xp[2][TT][1024];   // gate preactivations x@W_ih.T + b_ih + b_hh
__device__ float    g_lstm[TT * 512];    // [T][512] = concat(hf, hb)
__device__ float    g_logits[TT * 8];    // [T][8] padded (7 used)
__device__ float    g_h[2][2][256];      // [dir][parity][256] hidden exchange buffer
__device__ unsigned g_ctr[2];            // per-direction arrival counters

// ---------------- reset (graph replays reuse counters) --------------------
__global__ void reset_kernel() {
    if (threadIdx.x < 2) g_ctr[threadIdx.x] = 0u;
}

// ---------------- x_proj GEMM: C[t][n] = emb[sent[t]] . W[n] + b1[n]+b2[n]
// 64x64 tile, BK=16, 256 threads, 4x4 microtile
__global__ void __launch_bounds__(256) xproj_kernel(
    const int* __restrict__ sent, const float* __restrict__ emb,
    const float* __restrict__ Wf, const float* __restrict__ b1f, const float* __restrict__ b2f,
    const float* __restrict__ Wb, const float* __restrict__ b1b, const float* __restrict__ b2b)
{
    int dir = blockIdx.z;
    const float* W  = dir ? Wb  : Wf;
    const float* b1 = dir ? b1b : b1f;
    const float* b2 = dir ? b2b : b2f;
    int t0 = blockIdx.x * 64;
    int n0 = blockIdx.y * 64;

    __shared__ __align__(16) float As[16][68];
    __shared__ __align__(16) float Bs[16][68];
    __shared__ int sent_s[64];

    int tid = threadIdx.x;
    if (tid < 64) sent_s[tid] = sent[t0 + tid];
    __syncthreads();

    int tx = tid & 15;      // 0..15 -> n microtile
    int ty = tid >> 4;      // 0..15 -> t microtile
    float acc[4][4];
#pragma unroll
    for (int i = 0; i < 4; i++)
#pragma unroll
        for (int j = 0; j < 4; j++) acc[i][j] = 0.f;

    int kk = tid & 15;
    int m0 = tid >> 4;
    for (int k0 = 0; k0 < 256; k0 += 16) {
#pragma unroll
        for (int r = 0; r < 4; r++) {
            int mm = m0 + 16 * r;
            As[kk][mm] = emb[(long long)sent_s[mm] * 256 + k0 + kk];
            Bs[kk][mm] = W[(long long)(n0 + mm) * 256 + k0 + kk];
        }
        __syncthreads();
#pragma unroll
        for (int k2 = 0; k2 < 16; k2++) {
            float4 fa = *(const float4*)&As[k2][ty * 4];
            float4 fb = *(const float4*)&Bs[k2][tx * 4];
            float a[4] = {fa.x, fa.y, fa.z, fa.w};
            float b[4] = {fb.x, fb.y, fb.z, fb.w};
#pragma unroll
            for (int i = 0; i < 4; i++)
#pragma unroll
                for (int j = 0; j < 4; j++)
                    acc[i][j] = fmaf(a[i], b[j], acc[i][j]);
        }
        __syncthreads();
    }
#pragma unroll
    for (int i = 0; i < 4; i++) {
        int t = t0 + ty * 4 + i;
#pragma unroll
        for (int j = 0; j < 4; j++) {
            int n = n0 + tx * 4 + j;
            g_xp[dir][t][n] = acc[i][j] + b1[n] + b2[n];
        }
    }
}

// ---------------- BiLSTM recurrence -------------------------------------
// grid = 32 blocks (16 per direction), 256 threads.
// Block (dir, rank) owns 16 hidden units j = rank*16..rank*16+15 (all 4 gates
// = 64 rows of W_hh). Each row's 256-dot is split across 4 threads (q=0..3),
// weights in registers, h in smem (4 bank-staggered quarter replicas).
// Cross-block h exchange through double-buffered L2 buffer + counter spin.
__global__ void __launch_bounds__(256, 1) lstm_kernel(
    const float* __restrict__ Whhf, const float* __restrict__ Whhb,
    const float* __restrict__ h0, const float* __restrict__ c0)
{
    int bx   = blockIdx.x;
    int dir  = bx >> 4;
    int rank = bx & 15;
    const float* Whh = dir ? Whhb : Whhf;

    int tid  = threadIdx.x;
    int r    = tid >> 2;          // local row 0..63
    int q    = tid & 3;           // k-quarter
    int gate = r >> 4;            // 0..3 (i,f,g,o)
    int jl   = r & 15;
    int jglob = rank * 16 + jl;
    int rowg  = gate * 256 + jglob;

    // weights for this (row, quarter) in registers: 64 floats
    float4 w[16];
    const float4* wsrc = (const float4*)(Whh + (long long)rowg * 256 + q * 64);
#pragma unroll
    for (int i = 0; i < 16; i++) w[i] = wsrc[i];

    __shared__ __align__(16) float h_s[4 * 68];  // quarter q at offset q*68
    __shared__ float gate_s[64];

    h_s[(tid >> 6) * 68 + (tid & 63)] = h0[dir * 256 + tid];

    bool isleader = (q == 0);
    bool isg0 = (tid < 64) && isleader;          // r<16 -> owns hidden unit jl
    float cst = isg0 ? c0[dir * 256 + jglob] : 0.f;
    __syncthreads();

    const float* xbase = &g_xp[dir][0][0];
    const float4* hp = (const float4*)(h_s + q * 68);

    for (int s = 0; s < TT; s++) {
        int t = dir ? (TT - 1 - s) : s;

        float xv = 0.f;
        if (isleader) xv = __ldcg(xbase + (long long)t * 1024 + rowg);

        float a0 = 0.f, a1 = 0.f;
#pragma unroll
        for (int i = 0; i < 16; i += 2) {
            float4 ha = hp[i], hb = hp[i + 1];
            float4 wa = w[i], wb = w[i + 1];
            a0 = fmaf(wa.x, ha.x, a0); a0 = fmaf(wa.y, ha.y, a0);
            a0 = fmaf(wa.z, ha.z, a0); a0 = fmaf(wa.w, ha.w, a0);
            a1 = fmaf(wb.x, hb.x, a1); a1 = fmaf(wb.y, hb.y, a1);
            a1 = fmaf(wb.z, hb.z, a1); a1 = fmaf(wb.w, hb.w, a1);
        }
        float ssum = a0 + a1;
        ssum += __shfl_xor_sync(0xffffffffu, ssum, 1);
        ssum += __shfl_xor_sync(0xffffffffu, ssum, 2);
        if (isleader) gate_s[r] = ssum + xv;
        __syncthreads();

        if (isg0) {
            float gi = gate_s[jl];
            float gf = gate_s[16 + jl];
            float gg = gate_s[32 + jl];
            float go = gate_s[48 + jl];
            gi = 1.f / (1.f + expf(-gi));
            gf = 1.f / (1.f + expf(-gf));
            go = 1.f / (1.f + expf(-go));
            gg = tanhf(gg);
            cst = gf * cst + gi * gg;
            float hv = go * tanhf(cst);
            g_h[dir][s & 1][jglob] = hv;
            g_lstm[(long long)t * 512 + dir * 256 + jglob] = hv;
            __threadfence();                 // release writes before arrival
        }
        __syncthreads();

        if (tid == 0) {
            atomicAdd(&g_ctr[dir], 1u);
            unsigned target = (unsigned)NBLK * (unsigned)(s + 1);
            while (*((volatile unsigned*)&g_ctr[dir]) < target) { }
        }
        __syncthreads();

        if (s < TT - 1) {
            float hv = __ldcg(&g_h[dir][s & 1][tid]);   // L2-coherent read
            h_s[(tid >> 6) * 68 + (tid & 63)] = hv;
        }
        __syncthreads();
    }
}

// ---------------- logits = lstm_out @ W_out.T + b_out --------------------
__global__ void __launch_bounds__(256) logits_kernel(
    const float* __restrict__ Wout, const float* __restrict__ bout)
{
    __shared__ float Ws[7 * 512];
    int tid = threadIdx.x;
    for (int i = tid; i < 7 * 512; i += 256) Ws[i] = Wout[i];
    __syncthreads();

    int t = blockIdx.x * 8 + (tid >> 5);
    int lane = tid & 31;
    float acc[7];
#pragma unroll
    for (int j = 0; j < 7; j++) acc[j] = 0.f;
#pragma unroll
    for (int i = 0; i < 16; i++) {
        int k = lane + 32 * i;
        float v = g_lstm[(long long)t * 512 + k];
#pragma unroll
        for (int j = 0; j < 7; j++)
            acc[j] = fmaf(v, Ws[j * 512 + k], acc[j]);
    }
#pragma unroll
    for (int j = 0; j < 7; j++)
#pragma unroll
        for (int o = 16; o > 0; o >>= 1)
            acc[j] += __shfl_xor_sync(0xffffffffu, acc[j], o);
    if (lane < 7) g_logits[t * 8 + lane] = acc[lane] + bout[lane];
    else if (lane == 7) g_logits[t * 8 + 7] = 0.f;
}

// ---------------- Viterbi (forward + backtrack), single warp -------------
__global__ void viterbi_kernel(const float* __restrict__ trans,
                               float* __restrict__ out, int out_size)
{
    __shared__ unsigned bp_s[TT];                    // 21-bit packed backptrs
    __shared__ __align__(16) float feat_s[2][32][8]; // double-buffered logits

    int lane = threadIdx.x;
    float tn[7];
#pragma unroll
    for (int p = 0; p < 7; p++) tn[p] = (lane < 7) ? trans[lane * 7 + p] : -3.0e38f;
    float fv = (lane == 5) ? 0.f : -10000.f;         // START=5
    if (lane >= 7) fv = -3.0e38f;
    float tstop = (lane < 7) ? trans[6 * 7 + lane] : -3.0e38f;  // STOP=6 row

    // preload tile 0
    float4 p0 = *(const float4*)&g_logits[lane * 8];
    float4 p1 = *(const float4*)&g_logits[lane * 8 + 4];
    *(float4*)&feat_s[0][lane][0] = p0;
    *(float4*)&feat_s[0][lane][4] = p1;
    __syncwarp();

    for (int tile = 0; tile < TT / 32; tile++) {
        int buf = tile & 1;
        if (tile < TT / 32 - 1) {                    // prefetch next tile (LDG in flight)
            const float* src = &g_logits[((tile + 1) * 32 + lane) * 8];
            p0 = *(const float4*)src;
            p1 = *(const float4*)(src + 4);
        }
#pragma unroll 4
        for (int s2 = 0; s2 < 32; s2++) {
            int t = tile * 32 + s2;
            float best = -3.0e38f; int bi = 0;
#pragma unroll
            for (int p = 0; p < 7; p++) {
                float v = __shfl_sync(0xffffffffu, fv, p);
                float sc = v + tn[p];
                if (sc > best) { best = sc; bi = p; }
            }
            float feat = feat_s[buf][s2][lane & 7];
            fv = best + feat;
            unsigned contrib = (lane < 7) ? ((unsigned)bi << (3 * lane)) : 0u;
            unsigned word = __reduce_or_sync(0xffffffffu, contrib);
            if (lane == 0) bp_s[t] = word;
        }
        __syncwarp();
        if (tile < TT / 32 - 1) {
            *(float4*)&feat_s[buf ^ 1][lane][0] = p0;
            *(float4*)&feat_s[buf ^ 1][lane][4] = p1;
        }
        __syncwarp();
    }

    float term = fv + tstop;
    float bestv = -3.0e38f; int bestn = 0;
#pragma unroll
    for (int n = 0; n < 7; n++) {
        float v = __shfl_sync(0xffffffffu, term, n);
        if (v > bestv) { bestv = v; bestn = n; }
    }
    for (int i = 1 + TT + lane; i < out_size; i += 32) out[i] = 0.f;  // safety fill
    if (lane == 0) {
        out[0] = bestv;
        int tag = bestn;
        for (int t = TT - 1; t >= 0; t--) {
            out[1 + t] = (float)tag;
            tag = (int)((bp_s[t] >> (3 * tag)) & 7u);
        }
    }
}

// ---------------- launch ---------------------------------------------------
extern "C" void kernel_launch(void* const* d_in, const int* in_sizes, int n_in,
                              void* d_out, int out_size)
{
    const int*   sent  = (const int*)d_in[0];
    const float* emb   = (const float*)d_in[1];
    const float* Wihf  = (const float*)d_in[2];
    const float* Whhf  = (const float*)d_in[3];
    const float* bihf  = (const float*)d_in[4];
    const float* bhhf  = (const float*)d_in[5];
    const float* Wihb  = (const float*)d_in[6];
    const float* Whhb  = (const float*)d_in[7];
    const float* bihb  = (const float*)d_in[8];
    const float* bhhb  = (const float*)d_in[9];
    const float* h0    = (const float*)d_in[10];
    const float* c0    = (const float*)d_in[11];
    const float* Wout  = (const float*)d_in[12];
    const float* bout  = (const float*)d_in[13];
    const float* trans = (const float*)d_in[14];
    float* out = (float*)d_out;

    reset_kernel<<<1, 32>>>();
    xproj_kernel<<<dim3(TT / 64, 1024 / 64, 2), 256>>>(
        sent, emb, Wihf, bihf, bhhf, Wihb, bihb, bhhb);
    lstm_kernel<<<2 * NBLK, 256>>>(Whhf, Whhb, h0, c0);
    logits_kernel<<<TT / 8, 256>>>(Wout, bout);
    viterbi_kernel<<<1, 32>>>(trans, out, out_size);
}

// round 3
// speedup vs baseline: 1.2574x; 1.2574x over previous
#include <cuda_runtime.h>
#include <math.h>

#define TT 8192
#define NCL 8     // CTAs per direction (= cluster size) in the LSTM kernel

// ---------------- scratch (static device globals; no allocation) ----------
__device__ float g_xp[2][TT][1024];   // gate preactivations x@W_ih.T + b_ih + b_hh
__device__ float g_lstm[TT * 512];    // [T][512] = concat(hf, hb)
__device__ float g_logits[TT * 8];    // [T][8] padded (7 used)

__device__ __forceinline__ unsigned sm_addr(const void* p) {
    return (unsigned)__cvta_generic_to_shared(p);
}

// ---------------- x_proj GEMM: C[t][n] = emb[sent[t]] . W[n] + b1[n]+b2[n]
// 64x64 tile, BK=16, 256 threads, 4x4 microtile
__global__ void __launch_bounds__(256) xproj_kernel(
    const int* __restrict__ sent, const float* __restrict__ emb,
    const float* __restrict__ Wf, const float* __restrict__ b1f, const float* __restrict__ b2f,
    const float* __restrict__ Wb, const float* __restrict__ b1b, const float* __restrict__ b2b)
{
    int dir = blockIdx.z;
    const float* W  = dir ? Wb  : Wf;
    const float* b1 = dir ? b1b : b1f;
    const float* b2 = dir ? b2b : b2f;
    int t0 = blockIdx.x * 64;
    int n0 = blockIdx.y * 64;

    __shared__ __align__(16) float As[16][68];
    __shared__ __align__(16) float Bs[16][68];
    __shared__ int sent_s[64];

    int tid = threadIdx.x;
    if (tid < 64) sent_s[tid] = sent[t0 + tid];
    __syncthreads();

    int tx = tid & 15;
    int ty = tid >> 4;
    float acc[4][4];
#pragma unroll
    for (int i = 0; i < 4; i++)
#pragma unroll
        for (int j = 0; j < 4; j++) acc[i][j] = 0.f;

    int kk = tid & 15;
    int m0 = tid >> 4;
    for (int k0 = 0; k0 < 256; k0 += 16) {
#pragma unroll
        for (int r = 0; r < 4; r++) {
            int mm = m0 + 16 * r;
            As[kk][mm] = emb[(long long)sent_s[mm] * 256 + k0 + kk];
            Bs[kk][mm] = W[(long long)(n0 + mm) * 256 + k0 + kk];
        }
        __syncthreads();
#pragma unroll
        for (int k2 = 0; k2 < 16; k2++) {
            float4 fa = *(const float4*)&As[k2][ty * 4];
            float4 fb = *(const float4*)&Bs[k2][tx * 4];
            float a[4] = {fa.x, fa.y, fa.z, fa.w};
            float b[4] = {fb.x, fb.y, fb.z, fb.w};
#pragma unroll
            for (int i = 0; i < 4; i++)
#pragma unroll
                for (int j = 0; j < 4; j++)
                    acc[i][j] = fmaf(a[i], b[j], acc[i][j]);
        }
        __syncthreads();
    }
#pragma unroll
    for (int i = 0; i < 4; i++) {
        int t = t0 + ty * 4 + i;
#pragma unroll
        for (int j = 0; j < 4; j++) {
            int n = n0 + tx * 4 + j;
            g_xp[dir][t][n] = acc[i][j] + b1[n] + b2[n];
        }
    }
}

// ---------------- BiLSTM recurrence: DSMEM-cluster persistent kernel -----
// grid = 16 CTAs, cluster (8,1,1): cluster 0 = forward dir, cluster 1 = backward.
// CTA rank owns hidden units jglob = rank*32..rank*32+31 (128 W_hh rows, all
// in registers: 128 floats/thread). h vector (256 floats) lives in smem,
// double-buffered by step parity, split: h[0..127] at off 0, h[128..255] at
// off 132 (bank-staggered so the two half-warp broadcast groups don't clash).
// Exchange: 8 pusher threads write the CTA's 32 new h values into every
// peer's smem via st.shared::cluster, then st.release a monotonic flag.
// Consumers poll local flags (relaxed v4 LDS) + one fence.acq_rel.cluster.
__global__ void __cluster_dims__(NCL, 1, 1) __launch_bounds__(256, 1) lstm_kernel(
    const float* __restrict__ Whhf, const float* __restrict__ Whhb,
    const float* __restrict__ h0, const float* __restrict__ c0)
{
    __shared__ __align__(16) float h_buf[2][264];
    __shared__ __align__(16) float h_stage[32];
    __shared__ float gate_s[128];
    __shared__ __align__(16) unsigned flags[8];

    unsigned rank;
    asm("mov.u32 %0, %%cluster_ctarank;" : "=r"(rank));
    int dir = blockIdx.x >> 3;
    int tid = threadIdx.x;
    int lr = tid >> 1;            // local row 0..127  (= gate*32 + jl)
    int halfsel = tid & 1;        // which 128-half of the 256-dot
    int gate = lr >> 5;
    int jl = lr & 31;
    int jglob = (int)rank * 32 + jl;
    int rowg = gate * 256 + jglob;
    const float* Whh = dir ? Whhb : Whhf;

    // 32 float4 weights in registers
    float4 w[32];
    const float4* wsrc = (const float4*)(Whh + (long long)rowg * 256 + halfsel * 128);
#pragma unroll
    for (int i = 0; i < 32; i++) w[i] = wsrc[i];

    // init h(0), flags, c
    h_buf[0][tid < 128 ? tid : 132 + (tid - 128)] = h0[dir * 256 + tid];
    if (tid < 8) flags[tid] = 0u;
    float cst = (tid < 32) ? c0[dir * 256 + (int)rank * 32 + tid] : 0.f;
    __syncthreads();
    asm volatile("barrier.cluster.arrive.aligned;" ::: "memory");
    asm volatile("barrier.cluster.wait.aligned;" ::: "memory");

    unsigned flags_sa = sm_addr(flags);
    unsigned hbuf_sa  = sm_addr(h_buf);
    int myoff = ((int)rank < 4) ? (int)rank * 32 : 132 + (int)rank * 32 - 128;

    const float* xbase = &g_xp[dir][0][0];
    float xv = 0.f;
    {
        int t1 = dir ? (TT - 1) : 0;
        if (halfsel == 0) xv = __ldcg(xbase + (long long)t1 * 1024 + rowg);
    }

    for (int s = 1; s <= TT; s++) {
        int t = dir ? (TT - s) : (s - 1);

        // ---- wait until all 8 producers published h(s-1) ----
        if (s > 1) {
            unsigned need = (unsigned)(s - 1);
            unsigned f0, f1, f2, f3, f4, f5, f6, f7;
            while (true) {
                asm volatile("ld.volatile.shared.v4.u32 {%0,%1,%2,%3}, [%4];"
                             : "=r"(f0), "=r"(f1), "=r"(f2), "=r"(f3) : "r"(flags_sa));
                asm volatile("ld.volatile.shared.v4.u32 {%0,%1,%2,%3}, [%4];"
                             : "=r"(f4), "=r"(f5), "=r"(f6), "=r"(f7) : "r"(flags_sa + 16u));
                unsigned m01 = min(f0, f1), m23 = min(f2, f3);
                unsigned m45 = min(f4, f5), m67 = min(f6, f7);
                unsigned m = min(min(m01, m23), min(m45, m67));
                if (m >= need) break;
            }
            asm volatile("fence.acq_rel.cluster;" ::: "memory");
        }

        // ---- 128-dot partial (half of the 256-dot for row lr) ----
        const float4* hb4 = (const float4*)(&h_buf[(s - 1) & 1][halfsel * 132]);
        float a0 = 0.f, a1 = 0.f, a2 = 0.f, a3 = 0.f;
#pragma unroll
        for (int i = 0; i < 32; i += 4) {
            float4 hA = hb4[i + 0]; float4 wA = w[i + 0];
            a0 = fmaf(wA.x, hA.x, a0); a0 = fmaf(wA.y, hA.y, a0);
            a0 = fmaf(wA.z, hA.z, a0); a0 = fmaf(wA.w, hA.w, a0);
            float4 hB = hb4[i + 1]; float4 wB = w[i + 1];
            a1 = fmaf(wB.x, hB.x, a1); a1 = fmaf(wB.y, hB.y, a1);
            a1 = fmaf(wB.z, hB.z, a1); a1 = fmaf(wB.w, hB.w, a1);
            float4 hC = hb4[i + 2]; float4 wC = w[i + 2];
            a2 = fmaf(wC.x, hC.x, a2); a2 = fmaf(wC.y, hC.y, a2);
            a2 = fmaf(wC.z, hC.z, a2); a2 = fmaf(wC.w, hC.w, a2);
            float4 hD = hb4[i + 3]; float4 wD = w[i + 3];
            a3 = fmaf(wD.x, hD.x, a3); a3 = fmaf(wD.y, hD.y, a3);
            a3 = fmaf(wD.z, hD.z, a3); a3 = fmaf(wD.w, hD.w, a3);
        }
        float sum = (a0 + a1) + (a2 + a3);
        sum += __shfl_xor_sync(0xffffffffu, sum, 1);   // combine the two halves

        // prefetch next step's x while the tail of this step runs
        float xvn = 0.f;
        if (halfsel == 0 && s < TT) {
            int tn = dir ? (TT - 1 - s) : s;
            xvn = __ldcg(xbase + (long long)tn * 1024 + rowg);
        }
        if (halfsel == 0) gate_s[lr] = sum + xv;
        xv = xvn;
        __syncthreads();

        // ---- owners: activations + state update ----
        if (tid < 32) {
            float gi = gate_s[tid];
            float gf = gate_s[32 + tid];
            float gg = gate_s[64 + tid];
            float go = gate_s[96 + tid];
            gi = __fdividef(1.f, 1.f + __expf(-gi));
            gf = __fdividef(1.f, 1.f + __expf(-gf));
            go = __fdividef(1.f, 1.f + __expf(-go));
            gg = __fdividef(2.f, 1.f + __expf(-2.f * gg)) - 1.f;   // tanh
            cst = gf * cst + gi * gg;
            float th = __fdividef(2.f, 1.f + __expf(-2.f * cst)) - 1.f;
            float hv = go * th;
            h_stage[tid] = hv;
            __stcg(&g_lstm[(long long)t * 512 + dir * 256 + (int)rank * 32 + tid], hv);
        }
        __syncthreads();

        // ---- push h(s) slice to every peer's smem, then release flag ----
        if (tid < 8) {
            unsigned lsrc = hbuf_sa + (unsigned)((((s & 1) * 264) + myoff) * 4);
            unsigned dsth;
            asm("mapa.shared::cluster.u32 %0, %1, %2;"
                : "=r"(dsth) : "r"(lsrc), "r"((unsigned)tid));
            const float4* st4 = (const float4*)h_stage;
#pragma unroll
            for (int i = 0; i < 8; i++) {
                float4 v = st4[i];
                asm volatile("st.shared::cluster.v4.f32 [%0], {%1,%2,%3,%4};"
                             :: "r"(dsth + 16u * i),
                                "f"(v.x), "f"(v.y), "f"(v.z), "f"(v.w) : "memory");
            }
            unsigned lflag = flags_sa + 4u * rank;
            unsigned dstf;
            asm("mapa.shared::cluster.u32 %0, %1, %2;"
                : "=r"(dstf) : "r"(lflag), "r"((unsigned)tid));
            asm volatile("st.release.cluster.shared::cluster.u32 [%0], %1;"
                         :: "r"(dstf), "r"((unsigned)s) : "memory");
        }
    }
}

// ---------------- logits = lstm_out @ W_out.T + b_out --------------------
__global__ void __launch_bounds__(256) logits_kernel(
    const float* __restrict__ Wout, const float* __restrict__ bout)
{
    __shared__ float Ws[7 * 512];
    int tid = threadIdx.x;
    for (int i = tid; i < 7 * 512; i += 256) Ws[i] = Wout[i];
    __syncthreads();

    int t = blockIdx.x * 8 + (tid >> 5);
    int lane = tid & 31;
    float acc[7];
#pragma unroll
    for (int j = 0; j < 7; j++) acc[j] = 0.f;
#pragma unroll
    for (int i = 0; i < 16; i++) {
        int k = lane + 32 * i;
        float v = g_lstm[(long long)t * 512 + k];
#pragma unroll
        for (int j = 0; j < 7; j++)
            acc[j] = fmaf(v, Ws[j * 512 + k], acc[j]);
    }
#pragma unroll
    for (int j = 0; j < 7; j++)
#pragma unroll
        for (int o = 16; o > 0; o >>= 1)
            acc[j] += __shfl_xor_sync(0xffffffffu, acc[j], o);
    if (lane < 7) g_logits[t * 8 + lane] = acc[lane] + bout[lane];
    else if (lane == 7) g_logits[t * 8 + 7] = 0.f;
}

// ---------------- Viterbi (forward + backtrack), single warp -------------
__global__ void viterbi_kernel(const float* __restrict__ trans,
                               float* __restrict__ out, int out_size)
{
    __shared__ unsigned bp_s[TT];                    // 21-bit packed backptrs
    __shared__ __align__(16) float feat_s[2][32][8]; // double-buffered logits

    int lane = threadIdx.x;
    float tn[7];
#pragma unroll
    for (int p = 0; p < 7; p++) tn[p] = (lane < 7) ? trans[lane * 7 + p] : -3.0e38f;
    float fv = (lane == 5) ? 0.f : -10000.f;         // START=5
    if (lane >= 7) fv = -3.0e38f;
    float tstop = (lane < 7) ? trans[6 * 7 + lane] : -3.0e38f;  // STOP=6 row

    float4 p0 = *(const float4*)&g_logits[lane * 8];
    float4 p1 = *(const float4*)&g_logits[lane * 8 + 4];
    *(float4*)&feat_s[0][lane][0] = p0;
    *(float4*)&feat_s[0][lane][4] = p1;
    __syncwarp();

    for (int tile = 0; tile < TT / 32; tile++) {
        int buf = tile & 1;
        if (tile < TT / 32 - 1) {
            const float* src = &g_logits[((tile + 1) * 32 + lane) * 8];
            p0 = *(const float4*)src;
            p1 = *(const float4*)(src + 4);
        }
#pragma unroll 4
        for (int s2 = 0; s2 < 32; s2++) {
            int t = tile * 32 + s2;
            float best = -3.0e38f; int bi = 0;
#pragma unroll
            for (int p = 0; p < 7; p++) {
                float v = __shfl_sync(0xffffffffu, fv, p);
                float sc = v + tn[p];
                if (sc > best) { best = sc; bi = p; }
            }
            float feat = feat_s[buf][s2][lane & 7];
            fv = best + feat;
            unsigned contrib = (lane < 7) ? ((unsigned)bi << (3 * lane)) : 0u;
            unsigned word = __reduce_or_sync(0xffffffffu, contrib);
            if (lane == 0) bp_s[t] = word;
        }
        __syncwarp();
        if (tile < TT / 32 - 1) {
            *(float4*)&feat_s[buf ^ 1][lane][0] = p0;
            *(float4*)&feat_s[buf ^ 1][lane][4] = p1;
        }
        __syncwarp();
    }

    float term = fv + tstop;
    float bestv = -3.0e38f; int bestn = 0;
#pragma unroll
    for (int n = 0; n < 7; n++) {
        float v = __shfl_sync(0xffffffffu, term, n);
        if (v > bestv) { bestv = v; bestn = n; }
    }
    for (int i = 1 + TT + lane; i < out_size; i += 32) out[i] = 0.f;
    if (lane == 0) {
        out[0] = bestv;
        int tag = bestn;
        for (int t = TT - 1; t >= 0; t--) {
            out[1 + t] = (float)tag;
            tag = (int)((bp_s[t] >> (3 * tag)) & 7u);
        }
    }
}

// ---------------- launch ---------------------------------------------------
extern "C" void kernel_launch(void* const* d_in, const int* in_sizes, int n_in,
                              void* d_out, int out_size)
{
    const int*   sent  = (const int*)d_in[0];
    const float* emb   = (const float*)d_in[1];
    const float* Wihf  = (const float*)d_in[2];
    const float* Whhf  = (const float*)d_in[3];
    const float* bihf  = (const float*)d_in[4];
    const float* bhhf  = (const float*)d_in[5];
    const float* Wihb  = (const float*)d_in[6];
    const float* Whhb  = (const float*)d_in[7];
    const float* bihb  = (const float*)d_in[8];
    const float* bhhb  = (const float*)d_in[9];
    const float* h0    = (const float*)d_in[10];
    const float* c0    = (const float*)d_in[11];
    const float* Wout  = (const float*)d_in[12];
    const float* bout  = (const float*)d_in[13];
    const float* trans = (const float*)d_in[14];
    float* out = (float*)d_out;

    xproj_kernel<<<dim3(TT / 64, 1024 / 64, 2), 256>>>(
        sent, emb, Wihf, bihf, bhhf, Wihb, bihb, bhhb);
    lstm_kernel<<<2 * NCL, 256>>>(Whhf, Whhb, h0, c0);
    logits_kernel<<<TT / 8, 256>>>(Wout, bout);
    viterbi_kernel<<<1, 32>>>(trans, out, out_size);
}

// round 6
// speedup vs baseline: 1.2630x; 1.0044x over previous
#include <cuda_runtime.h>
#include <math.h>

#define TT 8192
#define NCL 8     // CTAs per direction (= cluster size) in the LSTM kernel

// ---------------- scratch (static device globals; no allocation) ----------
__device__ float g_xp[2][TT][1024];   // gate preactivations x@W_ih.T + b_ih + b_hh
__device__ float g_lstm[TT * 512];    // [T][512] = concat(hf, hb)
__device__ float g_logits[TT * 8];    // [T][8] padded (7 used)

__device__ __forceinline__ unsigned sm_addr(const void* p) {
    return (unsigned)__cvta_generic_to_shared(p);
}

// ---------------- x_proj GEMM: C[t][n] = emb[sent[t]] . W[n] + b1[n]+b2[n]
__global__ void __launch_bounds__(256) xproj_kernel(
    const int* __restrict__ sent, const float* __restrict__ emb,
    const float* __restrict__ Wf, const float* __restrict__ b1f, const float* __restrict__ b2f,
    const float* __restrict__ Wb, const float* __restrict__ b1b, const float* __restrict__ b2b)
{
    int dir = blockIdx.z;
    const float* W  = dir ? Wb  : Wf;
    const float* b1 = dir ? b1b : b1f;
    const float* b2 = dir ? b2b : b2f;
    int t0 = blockIdx.x * 64;
    int n0 = blockIdx.y * 64;

    __shared__ __align__(16) float As[16][68];
    __shared__ __align__(16) float Bs[16][68];
    __shared__ int sent_s[64];

    int tid = threadIdx.x;
    if (tid < 64) sent_s[tid] = sent[t0 + tid];
    __syncthreads();

    int tx = tid & 15;
    int ty = tid >> 4;
    float acc[4][4];
#pragma unroll
    for (int i = 0; i < 4; i++)
#pragma unroll
        for (int j = 0; j < 4; j++) acc[i][j] = 0.f;

    int kk = tid & 15;
    int m0 = tid >> 4;
    for (int k0 = 0; k0 < 256; k0 += 16) {
#pragma unroll
        for (int r = 0; r < 4; r++) {
            int mm = m0 + 16 * r;
            As[kk][mm] = emb[(long long)sent_s[mm] * 256 + k0 + kk];
            Bs[kk][mm] = W[(long long)(n0 + mm) * 256 + k0 + kk];
        }
        __syncthreads();
#pragma unroll
        for (int k2 = 0; k2 < 16; k2++) {
            float4 fa = *(const float4*)&As[k2][ty * 4];
            float4 fb = *(const float4*)&Bs[k2][tx * 4];
            float a[4] = {fa.x, fa.y, fa.z, fa.w};
            float b[4] = {fb.x, fb.y, fb.z, fb.w};
#pragma unroll
            for (int i = 0; i < 4; i++)
#pragma unroll
                for (int j = 0; j < 4; j++)
                    acc[i][j] = fmaf(a[i], b[j], acc[i][j]);
        }
        __syncthreads();
    }
#pragma unroll
    for (int i = 0; i < 4; i++) {
        int t = t0 + ty * 4 + i;
#pragma unroll
        for (int j = 0; j < 4; j++) {
            int n = n0 + tx * 4 + j;
            g_xp[dir][t][n] = acc[i][j] + b1[n] + b2[n];
        }
    }
}

// ---------------- BiLSTM recurrence: DSMEM-cluster persistent kernel -----
// Identical structure to the proven R3 kernel (14.19ms), except the per-step
// fence.acq_rel.cluster is replaced by 8 pairwise ld.acquire flag loads.
__global__ void __cluster_dims__(NCL, 1, 1) __launch_bounds__(256, 1) lstm_kernel(
    const float* __restrict__ Whhf, const float* __restrict__ Whhb,
    const float* __restrict__ h0, const float* __restrict__ c0)
{
    __shared__ __align__(16) float h_buf[2][264];
    __shared__ __align__(16) float h_stage[32];
    __shared__ float gate_s[128];
    __shared__ __align__(16) unsigned flags[8];

    unsigned rank;
    asm("mov.u32 %0, %%cluster_ctarank;" : "=r"(rank));
    int dir = blockIdx.x >> 3;
    int tid = threadIdx.x;
    int lr = tid >> 1;            // local row 0..127  (= gate*32 + jl)
    int halfsel = tid & 1;        // which 128-half of the 256-dot
    int gate = lr >> 5;
    int jl = lr & 31;
    int jglob = (int)rank * 32 + jl;
    int rowg = gate * 256 + jglob;
    const float* Whh = dir ? Whhb : Whhf;

    // 32 float4 weights in registers
    float4 w[32];
    const float4* wsrc = (const float4*)(Whh + (long long)rowg * 256 + halfsel * 128);
#pragma unroll
    for (int i = 0; i < 32; i++) w[i] = wsrc[i];

    // init h(0), flags, c
    h_buf[0][tid < 128 ? tid : 132 + (tid - 128)] = h0[dir * 256 + tid];
    if (tid < 8) flags[tid] = 0u;
    float cst = (tid < 32) ? c0[dir * 256 + (int)rank * 32 + tid] : 0.f;
    __syncthreads();
    asm volatile("barrier.cluster.arrive.aligned;" ::: "memory");
    asm volatile("barrier.cluster.wait.aligned;" ::: "memory");

    unsigned flags_sa = sm_addr(flags);
    unsigned hbuf_sa  = sm_addr(h_buf);
    int myoff = ((int)rank < 4) ? (int)rank * 32 : 132 + (int)rank * 32 - 128;

    const float* xbase = &g_xp[dir][0][0];
    float xv = 0.f;
    {
        int t1 = dir ? (TT - 1) : 0;
        if (halfsel == 0) xv = __ldcg(xbase + (long long)t1 * 1024 + rowg);
    }

    for (int s = 1; s <= TT; s++) {
        int t = dir ? (TT - s) : (s - 1);

        // ---- wait until all 8 producers published h(s-1) ----
        if (s > 1) {
            unsigned need = (unsigned)(s - 1);
            unsigned f0, f1, f2, f3, f4, f5, f6, f7;
            while (true) {
                asm volatile("ld.volatile.shared.v4.u32 {%0,%1,%2,%3}, [%4];"
                             : "=r"(f0), "=r"(f1), "=r"(f2), "=r"(f3) : "r"(flags_sa));
                asm volatile("ld.volatile.shared.v4.u32 {%0,%1,%2,%3}, [%4];"
                             : "=r"(f4), "=r"(f5), "=r"(f6), "=r"(f7) : "r"(flags_sa + 16u));
                unsigned m01 = min(f0, f1), m23 = min(f2, f3);
                unsigned m45 = min(f4, f5), m67 = min(f6, f7);
                unsigned m = min(min(m01, m23), min(m45, m67));
                if (m >= need) break;
            }
            // pairwise synchronize-with each producer's st.release (replaces
            // the ~490-cyc fence.acq_rel.cluster). Monotonic flags: a repeat
            // acquire load observes >= the released value already seen above.
#pragma unroll
            for (int i = 0; i < 8; i++) {
                unsigned tmpv;
                asm volatile("ld.acquire.cluster.shared::cta.u32 %0, [%1];"
                             : "=r"(tmpv) : "r"(flags_sa + 4u * i) : "memory");
            }
        }

        // ---- 128-dot partial (half of the 256-dot for row lr) ----
        const float4* hb4 = (const float4*)(&h_buf[(s - 1) & 1][halfsel * 132]);
        float a0 = 0.f, a1 = 0.f, a2 = 0.f, a3 = 0.f;
#pragma unroll
        for (int i = 0; i < 32; i += 4) {
            float4 hA = hb4[i + 0]; float4 wA = w[i + 0];
            a0 = fmaf(wA.x, hA.x, a0); a0 = fmaf(wA.y, hA.y, a0);
            a0 = fmaf(wA.z, hA.z, a0); a0 = fmaf(wA.w, hA.w, a0);
            float4 hB = hb4[i + 1]; float4 wB = w[i + 1];
            a1 = fmaf(wB.x, hB.x, a1); a1 = fmaf(wB.y, hB.y, a1);
            a1 = fmaf(wB.z, hB.z, a1); a1 = fmaf(wB.w, hB.w, a1);
            float4 hC = hb4[i + 2]; float4 wC = w[i + 2];
            a2 = fmaf(wC.x, hC.x, a2); a2 = fmaf(wC.y, hC.y, a2);
            a2 = fmaf(wC.z, hC.z, a2); a2 = fmaf(wC.w, hC.w, a2);
            float4 hD = hb4[i + 3]; float4 wD = w[i + 3];
            a3 = fmaf(wD.x, hD.x, a3); a3 = fmaf(wD.y, hD.y, a3);
            a3 = fmaf(wD.z, hD.z, a3); a3 = fmaf(wD.w, hD.w, a3);
        }
        float sum = (a0 + a1) + (a2 + a3);
        sum += __shfl_xor_sync(0xffffffffu, sum, 1);   // combine the two halves

        // prefetch next step's x while the tail of this step runs
        float xvn = 0.f;
        if (halfsel == 0 && s < TT) {
            int tn = dir ? (TT - 1 - s) : s;
            xvn = __ldcg(xbase + (long long)tn * 1024 + rowg);
        }
        if (halfsel == 0) gate_s[lr] = sum + xv;
        xv = xvn;
        __syncthreads();

        // ---- owners: activations + state update ----
        if (tid < 32) {
            float gi = gate_s[tid];
            float gf = gate_s[32 + tid];
            float gg = gate_s[64 + tid];
            float go = gate_s[96 + tid];
            gi = __fdividef(1.f, 1.f + __expf(-gi));
            gf = __fdividef(1.f, 1.f + __expf(-gf));
            go = __fdividef(1.f, 1.f + __expf(-go));
            gg = __fdividef(2.f, 1.f + __expf(-2.f * gg)) - 1.f;   // tanh
            cst = gf * cst + gi * gg;
            float th = __fdividef(2.f, 1.f + __expf(-2.f * cst)) - 1.f;
            float hv = go * th;
            h_stage[tid] = hv;
            __stcg(&g_lstm[(long long)t * 512 + dir * 256 + (int)rank * 32 + tid], hv);
        }
        __syncthreads();

        // ---- push h(s) slice to every peer's smem, then release flag ----
        if (tid < 8) {
            unsigned lsrc = hbuf_sa + (unsigned)((((s & 1) * 264) + myoff) * 4);
            unsigned dsth;
            asm("mapa.shared::cluster.u32 %0, %1, %2;"
                : "=r"(dsth) : "r"(lsrc), "r"((unsigned)tid));
            const float4* st4 = (const float4*)h_stage;
#pragma unroll
            for (int i = 0; i < 8; i++) {
                float4 v = st4[i];
                asm volatile("st.shared::cluster.v4.f32 [%0], {%1,%2,%3,%4};"
                             :: "r"(dsth + 16u * i),
                                "f"(v.x), "f"(v.y), "f"(v.z), "f"(v.w) : "memory");
            }
            unsigned lflag = flags_sa + 4u * rank;
            unsigned dstf;
            asm("mapa.shared::cluster.u32 %0, %1, %2;"
                : "=r"(dstf) : "r"(lflag), "r"((unsigned)tid));
            asm volatile("st.release.cluster.shared::cluster.u32 [%0], %1;"
                         :: "r"(dstf), "r"((unsigned)s) : "memory");
        }
    }
}

// ---------------- logits = lstm_out @ W_out.T + b_out --------------------
__global__ void __launch_bounds__(256) logits_kernel(
    const float* __restrict__ Wout, const float* __restrict__ bout)
{
    __shared__ float Ws[7 * 512];
    int tid = threadIdx.x;
    for (int i = tid; i < 7 * 512; i += 256) Ws[i] = Wout[i];
    __syncthreads();

    int t = blockIdx.x * 8 + (tid >> 5);
    int lane = tid & 31;
    float acc[7];
#pragma unroll
    for (int j = 0; j < 7; j++) acc[j] = 0.f;
#pragma unroll
    for (int i = 0; i < 16; i++) {
        int k = lane + 32 * i;
        float v = g_lstm[(long long)t * 512 + k];
#pragma unroll
        for (int j = 0; j < 7; j++)
            acc[j] = fmaf(v, Ws[j * 512 + k], acc[j]);
    }
#pragma unroll
    for (int j = 0; j < 7; j++)
#pragma unroll
        for (int o = 16; o > 0; o >>= 1)
            acc[j] += __shfl_xor_sync(0xffffffffu, acc[j], o);
    if (lane < 7) g_logits[t * 8 + lane] = acc[lane] + bout[lane];
    else if (lane == 7) g_logits[t * 8 + 7] = 0.f;
}

// ---------------- Viterbi: replicated-fv single warp ---------------------
__global__ void viterbi_kernel(const float* __restrict__ trans,
                               float* __restrict__ out, int out_size)
{
    __shared__ unsigned bp_s[TT];
    __shared__ __align__(16) float feat_s[2][32][8];

    int lane = threadIdx.x;
    int n = (lane < 7) ? lane : 0;           // each lane owns target tag n
    float tn[7], tsp[7], f[7];
#pragma unroll
    for (int p = 0; p < 7; p++) tn[p] = trans[n * 7 + p];
#pragma unroll
    for (int p = 0; p < 7; p++) tsp[p] = trans[6 * 7 + p];   // STOP row
#pragma unroll
    for (int p = 0; p < 7; p++) f[p] = (p == 5) ? 0.f : -10000.f;  // START=5

    float4 p0 = *(const float4*)&g_logits[lane * 8];
    float4 p1 = *(const float4*)&g_logits[lane * 8 + 4];
    *(float4*)&feat_s[0][lane][0] = p0;
    *(float4*)&feat_s[0][lane][4] = p1;
    __syncwarp();

    for (int tile = 0; tile < TT / 32; tile++) {
        int buf = tile & 1;
        if (tile < TT / 32 - 1) {
            const float* src = &g_logits[((tile + 1) * 32 + lane) * 8];
            p0 = *(const float4*)src;
            p1 = *(const float4*)(src + 4);
        }
#pragma unroll 4
        for (int s2 = 0; s2 < 32; s2++) {
            int t = tile * 32 + s2;
            float c[7];
#pragma unroll
            for (int p = 0; p < 7; p++) c[p] = f[p] + tn[p];
            float m01 = fmaxf(c[0], c[1]), m23 = fmaxf(c[2], c[3]);
            float m45 = fmaxf(c[4], c[5]);
            float m = fmaxf(fmaxf(m01, m23), fmaxf(m45, c[6]));
            // first-index argmax (exact equality; m is bitwise one of c[p])
            int bi = 6;
            bi = (c[5] == m) ? 5 : bi;
            bi = (c[4] == m) ? 4 : bi;
            bi = (c[3] == m) ? 3 : bi;
            bi = (c[2] == m) ? 2 : bi;
            bi = (c[1] == m) ? 1 : bi;
            bi = (c[0] == m) ? 0 : bi;
            float fnew = m + feat_s[buf][s2][n];
#pragma unroll
            for (int p = 0; p < 7; p++) f[p] = __shfl_sync(0xffffffffu, fnew, p);
            unsigned contrib = (lane < 7) ? ((unsigned)bi << (3 * lane)) : 0u;
            unsigned word = __reduce_or_sync(0xffffffffu, contrib);
            if (lane == 0) bp_s[t] = word;
        }
        __syncwarp();
        if (tile < TT / 32 - 1) {
            *(float4*)&feat_s[buf ^ 1][lane][0] = p0;
            *(float4*)&feat_s[buf ^ 1][lane][4] = p1;
        }
        __syncwarp();
    }

    // termination (replicated in every lane)
    float tm[7];
#pragma unroll
    for (int p = 0; p < 7; p++) tm[p] = f[p] + tsp[p];
    float m01 = fmaxf(tm[0], tm[1]), m23 = fmaxf(tm[2], tm[3]);
    float m45 = fmaxf(tm[4], tm[5]);
    float bestv = fmaxf(fmaxf(m01, m23), fmaxf(m45, tm[6]));
    int bestn = 6;
    bestn = (tm[5] == bestv) ? 5 : bestn;
    bestn = (tm[4] == bestv) ? 4 : bestn;
    bestn = (tm[3] == bestv) ? 3 : bestn;
    bestn = (tm[2] == bestv) ? 2 : bestn;
    bestn = (tm[1] == bestv) ? 1 : bestn;
    bestn = (tm[0] == bestv) ? 0 : bestn;

    for (int i = 1 + TT + lane; i < out_size; i += 32) out[i] = 0.f;
    if (lane == 0) {
        out[0] = bestv;
        int tag = bestn;
        for (int t = TT - 1; t >= 0; t--) {
            out[1 + t] = (float)tag;
            tag = (int)((bp_s[t] >> (3 * tag)) & 7u);
        }
    }
}

// ---------------- launch ---------------------------------------------------
extern "C" void kernel_launch(void* const* d_in, const int* in_sizes, int n_in,
                              void* d_out, int out_size)
{
    const int*   sent  = (const int*)d_in[0];
    const float* emb   = (const float*)d_in[1];
    const float* Wihf  = (const float*)d_in[2];
    const float* Whhf  = (const float*)d_in[3];
    const float* bihf  = (const float*)d_in[4];
    const float* bhhf  = (const float*)d_in[5];
    const float* Wihb  = (const float*)d_in[6];
    const float* Whhb  = (const float*)d_in[7];
    const float* bihb  = (const float*)d_in[8];
    const float* bhhb  = (const float*)d_in[9];
    const float* h0    = (const float*)d_in[10];
    const float* c0    = (const float*)d_in[11];
    const float* Wout  = (const float*)d_in[12];
    const float* bout  = (const float*)d_in[13];
    const float* trans = (const float*)d_in[14];
    float* out = (float*)d_out;

    xproj_kernel<<<dim3(TT / 64, 1024 / 64, 2), 256>>>(
        sent, emb, Wihf, bihf, bhhf, Wihb, bihb, bhhb);
    lstm_kernel<<<2 * NCL, 256>>>(Whhf, Whhb, h0, c0);
    logits_kernel<<<TT / 8, 256>>>(Wout, bout);
    viterbi_kernel<<<1, 32>>>(trans, out, out_size);
}